// round 13
// baseline (speedup 1.0000x reference)
#include <cuda_runtime.h>
#include <cuda_fp16.h>
#include <cstdint>
#include <math.h>

#define B_DIM 16
#define SQ    2048
#define SKV   2048
#define D_DIM 256
#define BQ    128
#define BK    64
#define NIT   (SKV / BK)
#define KC    (0.022097086912079608f * 1.4426950408889634f)  // (1/sqrt(2048)) * log2(e)

#define LDS   264          // fp16 Y row stride (elems), 528B
#define LDSB  528
#define LDQI  272          // int8 Q/Y row stride (bytes): 256 + 16 pad
#define LDP   72           // sP row stride (fp16 elems), 144B
#define LDPB  144

// smem layout (bytes)
#define OFF_QI 0
#define SZ_QI  (BQ * LDQI)                 // 34816 (int8 Q)
#define OFF_Y  (OFF_QI + SZ_QI)
#define SZ_Y   (BK * LDSB)                 // 33792 per buffer (x3, fp16 Y)
#define OFF_YI (OFF_Y + 3 * SZ_Y)          // 136192
#define SZ_YI  (BK * LDQI)                 // 17408 per buffer (x2, int8 Y)
#define OFF_P  (OFF_YI + 2 * SZ_YI)        // 171008
#define SZ_P   (BQ * LDPB)                 // 18432 per buffer (x2)
#define OFF_L  (OFF_P + 2 * SZ_P)          // 207872
#define SMEM_BYTES (OFF_L + 2 * BQ * 4)    // 208896

__device__ int8_t  g_xi8[(size_t)B_DIM * SQ * D_DIM];
__device__ int8_t  g_yi8[(size_t)B_DIM * SKV * D_DIM];
__device__ __half  g_yh [(size_t)B_DIM * SKV * D_DIM];
__device__ float   g_sxk[(size_t)B_DIM * SQ];    // x row scale * KC
__device__ float   g_sy [(size_t)B_DIM * SKV];   // y row scale

__device__ __forceinline__ uint32_t sptr(const void* p) {
    return (uint32_t)__cvta_generic_to_shared(p);
}

__device__ __forceinline__ void ldsm4(uint32_t* r, uint32_t a) {
    asm("ldmatrix.sync.aligned.m8n8.x4.shared.b16 {%0,%1,%2,%3}, [%4];"
        : "=r"(r[0]), "=r"(r[1]), "=r"(r[2]), "=r"(r[3]) : "r"(a) : "memory");
}
__device__ __forceinline__ void ldsm4t(uint32_t* r, uint32_t a) {
    asm("ldmatrix.sync.aligned.m8n8.x4.trans.shared.b16 {%0,%1,%2,%3}, [%4];"
        : "=r"(r[0]), "=r"(r[1]), "=r"(r[2]), "=r"(r[3]) : "r"(a) : "memory");
}
// S-GEMM: int8 inputs, s32 accumulate (m16n8k32)
__device__ __forceinline__ void mma_s8(int* c, const uint32_t* a, uint32_t b0, uint32_t b1) {
    asm("mma.sync.aligned.m16n8k32.row.col.s32.s8.s8.s32 "
        "{%0,%1,%2,%3}, {%4,%5,%6,%7}, {%8,%9}, {%0,%1,%2,%3};"
        : "+r"(c[0]), "+r"(c[1]), "+r"(c[2]), "+r"(c[3])
        : "r"(a[0]), "r"(a[1]), "r"(a[2]), "r"(a[3]), "r"(b0), "r"(b1));
}
// O-GEMM: fp16 inputs, f32 accumulate
__device__ __forceinline__ void mma_f32(float* c, const uint32_t* a, uint32_t b0, uint32_t b1) {
    asm("mma.sync.aligned.m16n8k16.row.col.f32.f16.f16.f32 "
        "{%0,%1,%2,%3}, {%4,%5,%6,%7}, {%8,%9}, {%0,%1,%2,%3};"
        : "+f"(c[0]), "+f"(c[1]), "+f"(c[2]), "+f"(c[3])
        : "r"(a[0]), "r"(a[1]), "r"(a[2]), "r"(a[3]), "r"(b0), "r"(b1));
}
__device__ __forceinline__ float ex2(float x) {
    float r; asm("ex2.approx.f32 %0, %1;" : "=f"(r) : "f"(x)); return r;
}
__device__ __forceinline__ void cpasync16(uint32_t dst, const void* src) {
    asm volatile("cp.async.cg.shared.global [%0], [%1], 16;" :: "r"(dst), "l"(src) : "memory");
}
#define CP_COMMIT() asm volatile("cp.async.commit_group;" ::: "memory")
#define CP_WAIT0()  asm volatile("cp.async.wait_group 0;" ::: "memory")

// -------- precompute: per-row int8 quant (x, y), fp16 y, row scales --------
__global__ void __launch_bounds__(256) quant_rows(const float* __restrict__ x,
                                                  const float* __restrict__ y) {
    const int warp = threadIdx.x >> 5, lane = threadIdx.x & 31;
    const int row = blockIdx.x * 8 + warp;
    const bool isY = (blockIdx.y != 0);
    const float* src = (isY ? y : x) + (size_t)row * D_DIM + lane * 8;
    float4 f0 = reinterpret_cast<const float4*>(src)[0];
    float4 f1 = reinterpret_cast<const float4*>(src)[1];
    float m = fmaxf(fmaxf(fmaxf(fabsf(f0.x), fabsf(f0.y)), fmaxf(fabsf(f0.z), fabsf(f0.w))),
                    fmaxf(fmaxf(fabsf(f1.x), fabsf(f1.y)), fmaxf(fabsf(f1.z), fabsf(f1.w))));
#pragma unroll
    for (int s = 16; s; s >>= 1) m = fmaxf(m, __shfl_xor_sync(0xffffffffu, m, s));
    m = fmaxf(m, 1e-20f);
    const float scale = m * (1.f / 127.f);
    const float inv   = 127.f / m;
    int q0 = __float2int_rn(f0.x * inv), q1 = __float2int_rn(f0.y * inv);
    int q2 = __float2int_rn(f0.z * inv), q3 = __float2int_rn(f0.w * inv);
    int q4 = __float2int_rn(f1.x * inv), q5 = __float2int_rn(f1.y * inv);
    int q6 = __float2int_rn(f1.z * inv), q7 = __float2int_rn(f1.w * inv);
    uint2 pk;
    pk.x = (q0 & 255) | ((q1 & 255) << 8) | ((q2 & 255) << 16) | ((q3 & 255) << 24);
    pk.y = (q4 & 255) | ((q5 & 255) << 8) | ((q6 & 255) << 16) | ((q7 & 255) << 24);
    int8_t* d8 = (isY ? g_yi8 : g_xi8) + (size_t)row * D_DIM + lane * 8;
    *reinterpret_cast<uint2*>(d8) = pk;
    if (isY) {
        __half2 h0 = __floats2half2_rn(f0.x, f0.y);
        __half2 h1 = __floats2half2_rn(f0.z, f0.w);
        __half2 h2 = __floats2half2_rn(f1.x, f1.y);
        __half2 h3 = __floats2half2_rn(f1.z, f1.w);
        uint4 hv;
        hv.x = *reinterpret_cast<uint32_t*>(&h0);
        hv.y = *reinterpret_cast<uint32_t*>(&h1);
        hv.z = *reinterpret_cast<uint32_t*>(&h2);
        hv.w = *reinterpret_cast<uint32_t*>(&h3);
        *reinterpret_cast<uint4*>(g_yh + (size_t)row * D_DIM + lane * 8) = hv;
        if (lane == 0) g_sy[row] = scale;
    } else {
        if (lane == 0) g_sxk[row] = scale * KC;
    }
}

extern __shared__ char smem_raw[];

__global__ void __launch_bounds__(256, 1)
fa_kernel(const float* __restrict__ x, const float* __restrict__ mask,
          float* __restrict__ out) {
    const int tid  = threadIdx.x;
    const int lane = tid & 31;
    const int warp = tid >> 5;
    // phase A roles: 4 q-groups x 2 kv-halves, warp tile 32x32
    const int wq = warp >> 1;
    const int ws = warp & 1;
    // phase B roles: 2 q-groups x 4 d-quarters, warp tile 64x64
    const int wq2 = warp >> 2;
    const int wd  = warp & 3;

    const int b  = blockIdx.y;
    const int q0 = blockIdx.x * BQ;

    const uint32_t sm = sptr(smem_raw);
    float* sL = reinterpret_cast<float*>(smem_raw + OFF_L);

    // ---- prologue: int8 Q + int8/fp16 Y tile 0 via cp.async ----
    const int8_t* xgi = g_xi8 + ((size_t)b * SQ + q0) * D_DIM;
    const int8_t* ygi = g_yi8 + (size_t)b * SKV * D_DIM;
    const __half* yg  = g_yh  + (size_t)b * SKV * D_DIM;
#pragma unroll
    for (int i = 0; i < 8; i++) {       // Q int8: 2048 x 16B units
        int unit = tid + (i << 8);
        int r = unit >> 4, u = unit & 15;
        cpasync16(sm + OFF_QI + r * LDQI + u * 16, xgi + (size_t)r * D_DIM + u * 16);
    }
#pragma unroll
    for (int i = 0; i < 8; i++) {       // Y fp16: 2048 units
        int unit = tid + (i << 8);
        int r = unit >> 5, u = unit & 31;
        cpasync16(sm + OFF_Y + r * LDSB + u * 16, yg + (size_t)r * D_DIM + u * 8);
    }
#pragma unroll
    for (int i = 0; i < 4; i++) {       // Y int8: 1024 units
        int unit = tid + (i << 8);
        int r = unit >> 4, u = unit & 15;
        cpasync16(sm + OFF_YI + r * LDQI + u * 16, ygi + (size_t)r * D_DIM + u * 16);
    }
    CP_COMMIT();
    CP_WAIT0();
    __syncthreads();

    // ---- precomputed addresses ----
    const int jb = lane >> 3;
    // phase A (int8): A frags from sQ (rows wq*32.., two 16-row halves)
    const uint32_t aX0 = sm + OFF_QI + (uint32_t)((wq * 32 + (lane & 15)) * LDQI + (lane >> 4) * 16);
    const uint32_t aX1 = aX0 + 16 * LDQI;
    // phase A (int8): B frags from sYI (kv rows ws*32..)
    const int bRow = (lane & 7) + ((jb >> 1) << 3);
    const int bColB = (jb & 1) * 16;
    const uint32_t bS0 = sm + OFF_YI + (uint32_t)((ws * 32 + bRow) * LDQI + bColB);
    // phase B: A frags from sP (rows wq2*64..)
    const uint32_t aP = sm + OFF_P + (uint32_t)(((wq2 * 64 + (lane & 15)) * LDP + ((lane >> 4) << 3)) << 1);
    // phase B: B frags from sY (fp16), k = kv, n = d -> trans
    const int vRow = (lane & 7) + ((jb & 1) << 3);
    const int vCol = ((jb >> 1) << 3) + wd * 64;
    const uint32_t bV = sm + OFF_Y + (uint32_t)(((vRow * LDS) + vCol) << 1);
    // P store base (phase A role)
    const uint32_t pSt = sm + OFF_P + (uint32_t)(((wq * 32 + (lane >> 2)) * LDP + ws * 32 + ((lane & 3) << 1)) << 1);
    // mask base (phase A role)
    const float* mBase = mask + ((size_t)(b * SQ + q0 + wq * 32 + (lane >> 2))) * SKV
                              + ws * 32 + ((lane & 3) << 1);
    // row scales (x) for this thread's 4 q-rows: wq*32 + {0,8,16,24} + g
    const float* sxp = g_sxk + (size_t)b * SQ + q0 + wq * 32 + (lane >> 2);
    const float sxk0 = sxp[0], sxk1 = sxp[8], sxk2 = sxp[16], sxk3 = sxp[24];
    // column scales (y) base for this thread's cols
    const float* syp = g_sy + (size_t)b * SKV + ws * 32 + ((lane & 3) << 1);

    float o[4][8][4];
#pragma unroll
    for (int mi = 0; mi < 4; mi++)
#pragma unroll
        for (int ni = 0; ni < 8; ni++) {
            o[mi][ni][0] = 0.f; o[mi][ni][1] = 0.f; o[mi][ni][2] = 0.f; o[mi][ni][3] = 0.f;
        }
    float lsum[4] = {0.f, 0.f, 0.f, 0.f};

    // fp16 Y ring x3: A/B offsets; int8 Y ping-pong x2 (lifetime = one iter)
    int yprev = 2, ycur = 0, ynext = 1;

    for (int it = 0; it < NIT; it++) {
        const uint32_t yiC = (uint32_t)(it & 1) * SZ_YI;

        // (1) prefetch next Y tiles (fp16 -> ring[ynext], int8 -> pingpong)
        if (it + 1 < NIT) {
            const __half*  ysrc  = yg  + (size_t)(it + 1) * BK * D_DIM;
            const int8_t*  ysrci = ygi + (size_t)(it + 1) * BK * D_DIM;
            const uint32_t ydst  = sm + OFF_Y  + (uint32_t)ynext * SZ_Y;
            const uint32_t ydsti = sm + OFF_YI + (uint32_t)((it + 1) & 1) * SZ_YI;
#pragma unroll
            for (int i = 0; i < 8; i++) {
                int unit = tid + (i << 8);
                int r = unit >> 5, u = unit & 31;
                cpasync16(ydst + r * LDSB + u * 16, ysrc + (size_t)r * D_DIM + u * 8);
            }
#pragma unroll
            for (int i = 0; i < 4; i++) {
                int unit = tid + (i << 8);
                int r = unit >> 4, u = unit & 15;
                cpasync16(ydsti + r * LDQI + u * 16, ysrci + (size_t)r * D_DIM + u * 16);
            }
            CP_COMMIT();
        }

        // (2) phase A: S = Q @ K^T (int8, k32 x 8 steps), s32 accum
        int cc[2][4][4];
#pragma unroll
        for (int mi = 0; mi < 2; mi++)
#pragma unroll
            for (int ni = 0; ni < 4; ni++) {
                cc[mi][ni][0] = 0; cc[mi][ni][1] = 0; cc[mi][ni][2] = 0; cc[mi][ni][3] = 0;
            }
#pragma unroll
        for (int ks = 0; ks < 8; ks++) {
            uint32_t a0[4], a1[4], b0[4], b1[4];
            ldsm4(a0, aX0 + (ks << 5));
            ldsm4(a1, aX1 + (ks << 5));
            ldsm4(b0, bS0 + yiC + (ks << 5));
            ldsm4(b1, bS0 + yiC + 16 * LDQI + (ks << 5));
            mma_s8(cc[0][0], a0, b0[0], b0[1]);
            mma_s8(cc[0][1], a0, b0[2], b0[3]);
            mma_s8(cc[0][2], a0, b1[0], b1[1]);
            mma_s8(cc[0][3], a0, b1[2], b1[3]);
            mma_s8(cc[1][0], a1, b0[0], b0[1]);
            mma_s8(cc[1][1], a1, b0[2], b0[3]);
            mma_s8(cc[1][2], a1, b1[0], b1[1]);
            mma_s8(cc[1][3], a1, b1[2], b1[3]);
        }

        // (3) mask + sy loads (LDG latency hides under phase B)
        float2 mv[2][2][4];
#pragma unroll
        for (int mi = 0; mi < 2; mi++)
#pragma unroll
            for (int hi = 0; hi < 2; hi++)
#pragma unroll
                for (int ni = 0; ni < 4; ni++)
                    mv[mi][hi][ni] = *reinterpret_cast<const float2*>(
                        mBase + (size_t)(mi * 16 + hi * 8) * SKV + (size_t)it * BK + ni * 8);
        float2 sy2[4];
#pragma unroll
        for (int ni = 0; ni < 4; ni++)
            sy2[ni] = *reinterpret_cast<const float2*>(syp + (size_t)it * BK + ni * 8);

        // (4) phase B for PREVIOUS iter: O += P[(it-1)%2] @ Y[yprev] (fp16)
        if (it > 0) {
            const uint32_t pOff = (uint32_t)((it - 1) & 1) * SZ_P;
            const uint32_t yoffP = (uint32_t)yprev * SZ_Y;
#pragma unroll
            for (int ks = 0; ks < 4; ks++) {
                uint32_t a[4][4];
#pragma unroll
                for (int mi = 0; mi < 4; mi++)
                    ldsm4(a[mi], aP + pOff + mi * 16 * LDPB + (ks << 5));
#pragma unroll
                for (int t2 = 0; t2 < 4; t2++) {
                    uint32_t bb[4];
                    ldsm4t(bb, bV + yoffP + ks * 16 * LDSB + (t2 << 5));
#pragma unroll
                    for (int mi = 0; mi < 4; mi++) {
                        mma_f32(o[mi][2 * t2],     a[mi], bb[0], bb[1]);
                        mma_f32(o[mi][2 * t2 + 1], a[mi], bb[2], bb[3]);
                    }
                }
            }
        }

        // (5) softmax with int8 dequant: p = 2^(c * sxk_row * (mask*sy_col)) -> P[it%2]
        {
            const uint32_t pW = pSt - sm + (uint32_t)(it & 1) * SZ_P;
#pragma unroll
            for (int mi = 0; mi < 2; mi++)
#pragma unroll
                for (int hi = 0; hi < 2; hi++) {
                    const float sxv = (mi == 0) ? (hi == 0 ? sxk0 : sxk1)
                                                : (hi == 0 ? sxk2 : sxk3);
                    float acc = 0.f;
#pragma unroll
                    for (int ni = 0; ni < 4; ni++) {
                        float m0 = mv[mi][hi][ni].x * sy2[ni].x * sxv;
                        float m1 = mv[mi][hi][ni].y * sy2[ni].y * sxv;
                        float p0 = ex2((float)cc[mi][ni][hi * 2 + 0] * m0);
                        float p1 = ex2((float)cc[mi][ni][hi * 2 + 1] * m1);
                        acc += p0 + p1;
                        __half2 hh = __floats2half2_rn(p0, p1);
                        *reinterpret_cast<__half2*>(
                            smem_raw + pW + (mi * 16 + hi * 8) * LDPB + ni * 16) = hh;
                    }
                    lsum[mi * 2 + hi] += acc;
                }
        }

        // (6) Y tiles landed + P visible for next iter
        if (it + 1 < NIT) CP_WAIT0();
        __syncthreads();

        int t = yprev; yprev = ycur; ycur = ynext; ynext = t;
    }

    // final phase B: O += P[(NIT-1)%2] @ Y[yprev]
    {
        const uint32_t pOff = (uint32_t)((NIT - 1) & 1) * SZ_P;
        const uint32_t yoffP = (uint32_t)yprev * SZ_Y;
#pragma unroll
        for (int ks = 0; ks < 4; ks++) {
            uint32_t a[4][4];
#pragma unroll
            for (int mi = 0; mi < 4; mi++)
                ldsm4(a[mi], aP + pOff + mi * 16 * LDPB + (ks << 5));
#pragma unroll
            for (int t2 = 0; t2 < 4; t2++) {
                uint32_t bb[4];
                ldsm4t(bb, bV + yoffP + ks * 16 * LDSB + (t2 << 5));
#pragma unroll
                for (int mi = 0; mi < 4; mi++) {
                    mma_f32(o[mi][2 * t2],     a[mi], bb[0], bb[1]);
                    mma_f32(o[mi][2 * t2 + 1], a[mi], bb[2], bb[3]);
                }
            }
        }
    }

    // ---------- epilogue: reduce l, write out = O/l + x ----------
#pragma unroll
    for (int s = 0; s < 4; s++) {
        float v = lsum[s];
        v += __shfl_xor_sync(0xffffffffu, v, 1);
        v += __shfl_xor_sync(0xffffffffu, v, 2);
        if ((lane & 3) == 0)
            sL[ws * BQ + wq * 32 + (s >> 1) * 16 + (s & 1) * 8 + (lane >> 2)] = v;
    }
    __syncthreads();

#pragma unroll
    for (int mi = 0; mi < 4; mi++)
#pragma unroll
        for (int hi = 0; hi < 2; hi++) {
            const int r = wq2 * 64 + mi * 16 + hi * 8 + (lane >> 2);
            const float inv = 1.f / (sL[r] + sL[BQ + r]);
            const size_t gr = (size_t)b * SQ + q0 + r;
            const float* xr = x + gr * D_DIM + wd * 64 + ((lane & 3) << 1);
            float* og = out + gr * D_DIM + wd * 64 + ((lane & 3) << 1);
#pragma unroll
            for (int ni = 0; ni < 8; ni++) {
                float2 xv = *reinterpret_cast<const float2*>(xr + ni * 8);
                float2 w;
                w.x = o[mi][ni][hi * 2 + 0] * inv + xv.x;
                w.y = o[mi][ni][hi * 2 + 1] * inv + xv.y;
                *reinterpret_cast<float2*>(og + ni * 8) = w;
            }
        }
}

extern "C" void kernel_launch(void* const* d_in, const int* in_sizes, int n_in,
                              void* d_out, int out_size) {
    const float* x    = (const float*)d_in[0];
    const float* y    = (const float*)d_in[1];
    const float* mask = (const float*)d_in[2];
    float* out        = (float*)d_out;

    dim3 qgrid((B_DIM * SQ) / 8, 2);    // 8 rows per block (one per warp)
    quant_rows<<<qgrid, 256>>>(x, y);

    cudaFuncSetAttribute(fa_kernel, cudaFuncAttributeMaxDynamicSharedMemorySize, SMEM_BYTES);
    dim3 grid(SQ / BQ, B_DIM);
    fa_kernel<<<grid, 256, SMEM_BYTES>>>(x, mask, out);
}

// round 14
// speedup vs baseline: 1.7774x; 1.7774x over previous
#include <cuda_runtime.h>
#include <cuda_fp16.h>
#include <cstdint>
#include <math.h>

#define B_DIM 16
#define SQ    2048
#define SKV   2048
#define D_DIM 256
#define BQ    64
#define BK    64
#define NIT   (SKV / BK)
#define KC    (0.022097086912079608f * 1.4426950408889634f)  // (1/sqrt(2048)) * log2(e)

#define NTHR  128

#define LDS   264          // sQ/sY row stride (fp16 elems), 528B
#define LDSB  528
#define LDP   72           // sP row stride (fp16 elems), 144B
#define LDPB  144

// smem layout (bytes) — sized so TWO CTAs fit per SM (2x111104 = 222208 <= 228KB)
#define OFF_Q 0
#define SZ_Q  (BQ * LDSB)                // 33792
#define OFF_Y (OFF_Q + SZ_Q)
#define SZ_Y  (BK * LDSB)                // 33792 per buffer (x2)
#define OFF_P (OFF_Y + 2 * SZ_Y)         // 101376
#define SZ_P  (BQ * LDPB)                // 9216 (single buffer)
#define OFF_L (OFF_P + SZ_P)             // 110592
#define SMEM_BYTES (OFF_L + 2 * BQ * 4)  // 111104

__device__ __half g_xh[(size_t)B_DIM * SQ * D_DIM];
__device__ __half g_yh[(size_t)B_DIM * SKV * D_DIM];

__device__ __forceinline__ uint32_t sptr(const void* p) {
    return (uint32_t)__cvta_generic_to_shared(p);
}

__device__ __forceinline__ void ldsm4(uint32_t* r, uint32_t a) {
    asm("ldmatrix.sync.aligned.m8n8.x4.shared.b16 {%0,%1,%2,%3}, [%4];"
        : "=r"(r[0]), "=r"(r[1]), "=r"(r[2]), "=r"(r[3]) : "r"(a) : "memory");
}
__device__ __forceinline__ void ldsm4t(uint32_t* r, uint32_t a) {
    asm("ldmatrix.sync.aligned.m8n8.x4.trans.shared.b16 {%0,%1,%2,%3}, [%4];"
        : "=r"(r[0]), "=r"(r[1]), "=r"(r[2]), "=r"(r[3]) : "r"(a) : "memory");
}
__device__ __forceinline__ void mma_f32(float* c, const uint32_t* a, uint32_t b0, uint32_t b1) {
    asm("mma.sync.aligned.m16n8k16.row.col.f32.f16.f16.f32 "
        "{%0,%1,%2,%3}, {%4,%5,%6,%7}, {%8,%9}, {%0,%1,%2,%3};"
        : "+f"(c[0]), "+f"(c[1]), "+f"(c[2]), "+f"(c[3])
        : "r"(a[0]), "r"(a[1]), "r"(a[2]), "r"(a[3]), "r"(b0), "r"(b1));
}
__device__ __forceinline__ float ex2(float x) {
    float r; asm("ex2.approx.f32 %0, %1;" : "=f"(r) : "f"(x)); return r;
}
__device__ __forceinline__ void cpasync16(uint32_t dst, const void* src) {
    asm volatile("cp.async.cg.shared.global [%0], [%1], 16;" :: "r"(dst), "l"(src) : "memory");
}
#define CP_COMMIT() asm volatile("cp.async.commit_group;" ::: "memory")
#define CP_WAIT0()  asm volatile("cp.async.wait_group 0;" ::: "memory")

// -------- pre-convert fp32 -> fp16 for x and y in one launch --------
__global__ void __launch_bounds__(256) convert_xy(const float* __restrict__ x,
                                                  const float* __restrict__ y) {
    const float* s = blockIdx.y ? y : x;
    __half* d = blockIdx.y ? g_yh : g_xh;
    size_t i = ((size_t)blockIdx.x * 256 + threadIdx.x) * 4;
    float4 f = *reinterpret_cast<const float4*>(s + i);
    __half2 h0 = __floats2half2_rn(f.x, f.y);
    __half2 h1 = __floats2half2_rn(f.z, f.w);
    uint2 u;
    u.x = *reinterpret_cast<uint32_t*>(&h0);
    u.y = *reinterpret_cast<uint32_t*>(&h1);
    *reinterpret_cast<uint2*>(d + i) = u;
}

extern __shared__ char smem_raw[];

__global__ void __launch_bounds__(NTHR, 2)
fa_kernel(const float* __restrict__ x, const float* __restrict__ mask,
          float* __restrict__ out) {
    const int tid  = threadIdx.x;
    const int lane = tid & 31;
    const int warp = tid >> 5;          // 0..3
    // phase A roles: 2 q-groups x 2 kv-halves, warp tile 32x32
    const int wq = warp >> 1;
    const int ws = warp & 1;
    // phase B roles: all 4 warps share q 0..63; each owns 64 of d=256
    const int wd = warp;

    const int b  = blockIdx.y;
    const int q0 = blockIdx.x * BQ;

    const uint32_t sm = sptr(smem_raw);
    float* sL = reinterpret_cast<float*>(smem_raw + OFF_L);

    // ---- prologue: Q tile + Y tile 0 via cp.async (fp16 sources) ----
    const __half* xg = g_xh + ((size_t)b * SQ + q0) * D_DIM;
    const __half* yg = g_yh + (size_t)b * SKV * D_DIM;
#pragma unroll
    for (int i = 0; i < 16; i++) {
        int unit = tid + (i << 7);      // 2048 units of 16B (32 per row)
        int r = unit >> 5, u = unit & 31;
        cpasync16(sm + OFF_Q + r * LDSB + u * 16, xg + (size_t)r * D_DIM + u * 8);
    }
#pragma unroll
    for (int i = 0; i < 16; i++) {
        int unit = tid + (i << 7);
        int r = unit >> 5, u = unit & 31;
        cpasync16(sm + OFF_Y + r * LDSB + u * 16, yg + (size_t)r * D_DIM + u * 8);
    }
    CP_COMMIT();
    CP_WAIT0();
    __syncthreads();

    // ---- precomputed addresses ----
    const int jb = lane >> 3;
    // phase A: A frags from sQ (rows wq*32.., two 16-row halves)
    const uint32_t aX0 = sm + OFF_Q + (uint32_t)(((wq * 32 + (lane & 15)) * LDS + ((lane >> 4) << 3)) << 1);
    const uint32_t aX1 = aX0 + 16 * LDSB;
    // phase A: B frags from sY (kv rows ws*32..), k = d, non-trans
    const int bRow = (lane & 7) + ((jb >> 1) << 3);
    const int bCol = (jb & 1) << 3;
    const uint32_t bS0 = sm + OFF_Y + (uint32_t)(((ws * 32 + bRow) * LDS + bCol) << 1);
    // phase B: A frags from sP (rows 0..63)
    const uint32_t aP = sm + OFF_P + (uint32_t)((((lane & 15)) * LDP + ((lane >> 4) << 3)) << 1);
    // phase B: B frags from sY, k = kv, n = d -> trans
    const int vRow = (lane & 7) + ((jb & 1) << 3);
    const int vCol = ((jb >> 1) << 3) + wd * 64;
    const uint32_t bV = sm + OFF_Y + (uint32_t)(((vRow * LDS) + vCol) << 1);
    // P store base (phase A role)
    const uint32_t pSt = sm + OFF_P + (uint32_t)(((wq * 32 + (lane >> 2)) * LDP + ws * 32 + ((lane & 3) << 1)) << 1);
    // mask base (phase A role)
    const float* mBase = mask + ((size_t)(b * SQ + q0 + wq * 32 + (lane >> 2))) * SKV
                              + ws * 32 + ((lane & 3) << 1);

    float o[4][8][4];
#pragma unroll
    for (int mi = 0; mi < 4; mi++)
#pragma unroll
        for (int ni = 0; ni < 8; ni++) {
            o[mi][ni][0] = 0.f; o[mi][ni][1] = 0.f; o[mi][ni][2] = 0.f; o[mi][ni][3] = 0.f;
        }
    float lsum[4] = {0.f, 0.f, 0.f, 0.f};

    for (int it = 0; it < NIT; it++) {
        const uint32_t yoffC = (uint32_t)(it & 1) * SZ_Y;

        // (1) prefetch next Y tile into the other buffer
        if (it + 1 < NIT) {
            const __half* ysrc = yg + (size_t)(it + 1) * BK * D_DIM;
            const uint32_t ydst = sm + OFF_Y + (uint32_t)((it & 1) ^ 1) * SZ_Y;
#pragma unroll
            for (int i = 0; i < 16; i++) {
                int unit = tid + (i << 7);
                int r = unit >> 5, u = unit & 31;
                cpasync16(ydst + r * LDSB + u * 16, ysrc + (size_t)r * D_DIM + u * 8);
            }
            CP_COMMIT();
        }

        // (2) phase A: S = Q @ K^T on Y[cur], warp tile 32x32, f32 accum.
        //     SOFTWARE-PIPELINED: fragments for ks+1 are issued before the
        //     mma block of ks, so the ~29cyc LDS latency hides under the
        //     8-mma (~56cyc) chain. Mask regs are NOT live here (moved below),
        //     giving ptxas the headroom for the 2-deep fragment ring.
        float c[2][4][4];
#pragma unroll
        for (int mi = 0; mi < 2; mi++)
#pragma unroll
            for (int ni = 0; ni < 4; ni++) {
                c[mi][ni][0] = 0.f; c[mi][ni][1] = 0.f; c[mi][ni][2] = 0.f; c[mi][ni][3] = 0.f;
            }
        {
            uint32_t a0[2][4], a1[2][4], b0[2][4], b1[2][4];
            ldsm4(a0[0], aX0);
            ldsm4(a1[0], aX1);
            ldsm4(b0[0], bS0 + yoffC);
            ldsm4(b1[0], bS0 + yoffC + 16 * LDSB);
#pragma unroll
            for (int ks = 0; ks < 16; ks++) {
                const int cur = ks & 1, nxt = cur ^ 1;
                if (ks < 15) {
                    const int kn = ks + 1;
                    ldsm4(a0[nxt], aX0 + (kn << 5));
                    ldsm4(a1[nxt], aX1 + (kn << 5));
                    ldsm4(b0[nxt], bS0 + yoffC + (kn << 5));
                    ldsm4(b1[nxt], bS0 + yoffC + 16 * LDSB + (kn << 5));
                }
                mma_f32(c[0][0], a0[cur], b0[cur][0], b0[cur][1]);
                mma_f32(c[0][1], a0[cur], b0[cur][2], b0[cur][3]);
                mma_f32(c[0][2], a0[cur], b1[cur][0], b1[cur][1]);
                mma_f32(c[0][3], a0[cur], b1[cur][2], b1[cur][3]);
                mma_f32(c[1][0], a1[cur], b0[cur][0], b0[cur][1]);
                mma_f32(c[1][1], a1[cur], b0[cur][2], b0[cur][3]);
                mma_f32(c[1][2], a1[cur], b1[cur][0], b1[cur][1]);
                mma_f32(c[1][3], a1[cur], b1[cur][2], b1[cur][3]);
            }
        }

        // (3) mask values (short live range: only until softmax below)
        float2 mv[2][2][4];
#pragma unroll
        for (int mi = 0; mi < 2; mi++)
#pragma unroll
            for (int hi = 0; hi < 2; hi++)
#pragma unroll
                for (int ni = 0; ni < 4; ni++)
                    mv[mi][hi][ni] = *reinterpret_cast<const float2*>(
                        mBase + (size_t)(mi * 16 + hi * 8) * SKV + (size_t)it * BK + ni * 8);

        // (4) softmax (no max shift: logits bounded) -> sP (fp16)
#pragma unroll
        for (int mi = 0; mi < 2; mi++)
#pragma unroll
            for (int hi = 0; hi < 2; hi++) {
                float acc = 0.f;
#pragma unroll
                for (int ni = 0; ni < 4; ni++) {
                    float p0 = ex2(c[mi][ni][hi * 2 + 0] * mv[mi][hi][ni].x * KC);
                    float p1 = ex2(c[mi][ni][hi * 2 + 1] * mv[mi][hi][ni].y * KC);
                    acc += p0 + p1;
                    __half2 hh = __floats2half2_rn(p0, p1);
                    *reinterpret_cast<__half2*>(
                        smem_raw + (pSt - sm) + (mi * 16 + hi * 8) * LDPB + ni * 16) = hh;
                }
                lsum[mi * 2 + hi] += acc;
            }
        __syncthreads();   // P visible (Y[cur] still in use; prefetch hits other buf)

        // (5) phase B: O += P @ Y[cur], warp tile 64x64, bb double-buffered
#pragma unroll
        for (int ks = 0; ks < 4; ks++) {
            uint32_t a[4][4];
#pragma unroll
            for (int mi = 0; mi < 4; mi++)
                ldsm4(a[mi], aP + mi * 16 * LDPB + (ks << 5));
            uint32_t bb[2][4];
            ldsm4t(bb[0], bV + yoffC + ks * 16 * LDSB);
#pragma unroll
            for (int t2 = 0; t2 < 4; t2++) {
                const int cur = t2 & 1, nxt = cur ^ 1;
                if (t2 < 3)
                    ldsm4t(bb[nxt], bV + yoffC + ks * 16 * LDSB + ((t2 + 1) << 5));
#pragma unroll
                for (int mi = 0; mi < 4; mi++) {
                    mma_f32(o[mi][2 * t2],     a[mi], bb[cur][0], bb[cur][1]);
                    mma_f32(o[mi][2 * t2 + 1], a[mi], bb[cur][2], bb[cur][3]);
                }
            }
        }

        // (6) Y[next] landed; P free; Y[cur] free after this point
        if (it + 1 < NIT) CP_WAIT0();
        __syncthreads();
    }

    // ---------- epilogue: reduce l, write out = O/l + x ----------
#pragma unroll
    for (int s = 0; s < 4; s++) {
        float v = lsum[s];
        v += __shfl_xor_sync(0xffffffffu, v, 1);
        v += __shfl_xor_sync(0xffffffffu, v, 2);
        if ((lane & 3) == 0)
            sL[ws * BQ + wq * 32 + (s >> 1) * 16 + (s & 1) * 8 + (lane >> 2)] = v;
    }
    __syncthreads();

#pragma unroll
    for (int mi = 0; mi < 4; mi++)
#pragma unroll
        for (int hi = 0; hi < 2; hi++) {
            const int r = mi * 16 + hi * 8 + (lane >> 2);
            const float inv = 1.f / (sL[r] + sL[BQ + r]);
            const size_t gr = (size_t)b * SQ + q0 + r;
            const float* xr = x + gr * D_DIM + wd * 64 + ((lane & 3) << 1);
            float* og = out + gr * D_DIM + wd * 64 + ((lane & 3) << 1);
#pragma unroll
            for (int ni = 0; ni < 8; ni++) {
                float2 xv = *reinterpret_cast<const float2*>(xr + ni * 8);
                float2 w;
                w.x = o[mi][ni][hi * 2 + 0] * inv + xv.x;
                w.y = o[mi][ni][hi * 2 + 1] * inv + xv.y;
                *reinterpret_cast<float2*>(og + ni * 8) = w;
            }
        }
}

extern "C" void kernel_launch(void* const* d_in, const int* in_sizes, int n_in,
                              void* d_out, int out_size) {
    const float* x    = (const float*)d_in[0];
    const float* y    = (const float*)d_in[1];
    const float* mask = (const float*)d_in[2];
    float* out        = (float*)d_out;

    dim3 cgrid((B_DIM * SQ * D_DIM) / (256 * 4), 2);
    convert_xy<<<cgrid, 256>>>(x, y);

    cudaFuncSetAttribute(fa_kernel, cudaFuncAttributeMaxDynamicSharedMemorySize, SMEM_BYTES);
    dim3 grid(SQ / BQ, B_DIM);
    fa_kernel<<<grid, NTHR, SMEM_BYTES>>>(x, mask, out);
}

// round 15
// speedup vs baseline: 1.8875x; 1.0620x over previous
#include <cuda_runtime.h>
#include <cuda_fp16.h>
#include <cstdint>
#include <math.h>

#define B_DIM 16
#define SQ    2048
#define SKV   2048
#define D_DIM 256
#define BQ    64
#define BK    64
#define NIT   (SKV / BK)
#define KC    (0.022097086912079608f * 1.4426950408889634f)  // (1/sqrt(2048)) * log2(e)

#define NTHR  128

#define LDS   264          // sQ/sY row stride (fp16 elems), 528B
#define LDSB  528
#define LDP   72           // sP row stride (fp16 elems), 144B
#define LDPB  144

// smem layout (bytes) — sized so TWO CTAs fit per SM (2x111104 = 222208 <= 228KB)
#define OFF_Q 0
#define SZ_Q  (BQ * LDSB)                // 33792
#define OFF_Y (OFF_Q + SZ_Q)
#define SZ_Y  (BK * LDSB)                // 33792 per buffer (x2)
#define OFF_P (OFF_Y + 2 * SZ_Y)         // 101376
#define SZ_P  (BQ * LDPB)                // 9216 (single buffer)
#define OFF_L (OFF_P + SZ_P)             // 110592
#define SMEM_BYTES (OFF_L + 2 * BQ * 4)  // 111104

__device__ __half g_yh[(size_t)B_DIM * SKV * D_DIM];

__device__ __forceinline__ uint32_t sptr(const void* p) {
    return (uint32_t)__cvta_generic_to_shared(p);
}

__device__ __forceinline__ void ldsm4(uint32_t* r, uint32_t a) {
    asm("ldmatrix.sync.aligned.m8n8.x4.shared.b16 {%0,%1,%2,%3}, [%4];"
        : "=r"(r[0]), "=r"(r[1]), "=r"(r[2]), "=r"(r[3]) : "r"(a) : "memory");
}
__device__ __forceinline__ void ldsm4t(uint32_t* r, uint32_t a) {
    asm("ldmatrix.sync.aligned.m8n8.x4.trans.shared.b16 {%0,%1,%2,%3}, [%4];"
        : "=r"(r[0]), "=r"(r[1]), "=r"(r[2]), "=r"(r[3]) : "r"(a) : "memory");
}
__device__ __forceinline__ void mma_f32(float* c, const uint32_t* a, uint32_t b0, uint32_t b1) {
    asm("mma.sync.aligned.m16n8k16.row.col.f32.f16.f16.f32 "
        "{%0,%1,%2,%3}, {%4,%5,%6,%7}, {%8,%9}, {%0,%1,%2,%3};"
        : "+f"(c[0]), "+f"(c[1]), "+f"(c[2]), "+f"(c[3])
        : "r"(a[0]), "r"(a[1]), "r"(a[2]), "r"(a[3]), "r"(b0), "r"(b1));
}
__device__ __forceinline__ float ex2(float x) {
    float r; asm("ex2.approx.f32 %0, %1;" : "=f"(r) : "f"(x)); return r;
}
__device__ __forceinline__ void cpasync16(uint32_t dst, const void* src) {
    asm volatile("cp.async.cg.shared.global [%0], [%1], 16;" :: "r"(dst), "l"(src) : "memory");
}
#define CP_COMMIT() asm volatile("cp.async.commit_group;" ::: "memory")
#define CP_WAIT0()  asm volatile("cp.async.wait_group 0;" ::: "memory")

// -------- pre-convert fp32 -> fp16 for y only (x handled in fa prologue) ----
// 4 independent float4 loads per thread for high MLP (DRAM-bandwidth shaped).
__global__ void __launch_bounds__(256) convert_y(const float* __restrict__ y) {
    size_t base = ((size_t)blockIdx.x * 256 + threadIdx.x) * 4;
    const size_t stride = (size_t)gridDim.x * 256 * 4;
#pragma unroll
    for (int j = 0; j < 4; j++) {
        size_t i = base + (size_t)j * stride;
        float4 f = *reinterpret_cast<const float4*>(y + i);
        __half2 h0 = __floats2half2_rn(f.x, f.y);
        __half2 h1 = __floats2half2_rn(f.z, f.w);
        uint2 u;
        u.x = *reinterpret_cast<uint32_t*>(&h0);
        u.y = *reinterpret_cast<uint32_t*>(&h1);
        *reinterpret_cast<uint2*>(g_yh + i) = u;
    }
}

extern __shared__ char smem_raw[];

__global__ void __launch_bounds__(NTHR, 2)
fa_kernel(const float* __restrict__ x, const float* __restrict__ mask,
          float* __restrict__ out) {
    const int tid  = threadIdx.x;
    const int lane = tid & 31;
    const int warp = tid >> 5;          // 0..3
    // phase A roles: 2 q-groups x 2 kv-halves, warp tile 32x32
    const int wq = warp >> 1;
    const int ws = warp & 1;
    // phase B roles: all 4 warps share q 0..63; each owns 64 of d=256
    const int wd = warp;

    const int b  = blockIdx.y;
    const int q0 = blockIdx.x * BQ;

    const uint32_t sm = sptr(smem_raw);
    float* sL = reinterpret_cast<float*>(smem_raw + OFF_L);

    // ---- prologue ----
    // Y tile 0 via cp.async (fp16 source); Q from fp32 x, converted inline.
    const float* xg32 = x + ((size_t)b * SQ + q0) * D_DIM;
    const __half* yg  = g_yh + (size_t)b * SKV * D_DIM;
#pragma unroll
    for (int i = 0; i < 16; i++) {
        int unit = tid + (i << 7);
        int r = unit >> 5, u = unit & 31;
        cpasync16(sm + OFF_Y + r * LDSB + u * 16, yg + (size_t)r * D_DIM + u * 8);
    }
    CP_COMMIT();
#pragma unroll
    for (int i = 0; i < 16; i++) {
        int unit = tid + (i << 7);      // 2048 units of 16B-fp16 (32 per row)
        int r = unit >> 5, u = unit & 31;
        const float* src = xg32 + (size_t)r * D_DIM + u * 8;
        float4 f0 = reinterpret_cast<const float4*>(src)[0];
        float4 f1 = reinterpret_cast<const float4*>(src)[1];
        __half2 h0 = __floats2half2_rn(f0.x, f0.y);
        __half2 h1 = __floats2half2_rn(f0.z, f0.w);
        __half2 h2 = __floats2half2_rn(f1.x, f1.y);
        __half2 h3 = __floats2half2_rn(f1.z, f1.w);
        uint4 v;
        v.x = *reinterpret_cast<uint32_t*>(&h0);
        v.y = *reinterpret_cast<uint32_t*>(&h1);
        v.z = *reinterpret_cast<uint32_t*>(&h2);
        v.w = *reinterpret_cast<uint32_t*>(&h3);
        *reinterpret_cast<uint4*>(smem_raw + OFF_Q + r * LDSB + u * 16) = v;
    }
    CP_WAIT0();
    __syncthreads();

    // ---- precomputed addresses ----
    const int jb = lane >> 3;
    // phase A: A frags from sQ (rows wq*32.., two 16-row halves)
    const uint32_t aX0 = sm + OFF_Q + (uint32_t)(((wq * 32 + (lane & 15)) * LDS + ((lane >> 4) << 3)) << 1);
    const uint32_t aX1 = aX0 + 16 * LDSB;
    // phase A: B frags from sY (kv rows ws*32..), k = d, non-trans
    const int bRow = (lane & 7) + ((jb >> 1) << 3);
    const int bCol = (jb & 1) << 3;
    const uint32_t bS0 = sm + OFF_Y + (uint32_t)(((ws * 32 + bRow) * LDS + bCol) << 1);
    // phase B: A frags from sP (rows 0..63)
    const uint32_t aP = sm + OFF_P + (uint32_t)((((lane & 15)) * LDP + ((lane >> 4) << 3)) << 1);
    // phase B: B frags from sY, k = kv, n = d -> trans
    const int vRow = (lane & 7) + ((jb & 1) << 3);
    const int vCol = ((jb >> 1) << 3) + wd * 64;
    const uint32_t bV = sm + OFF_Y + (uint32_t)(((vRow * LDS) + vCol) << 1);
    // P store base (phase A role)
    const uint32_t pSt = sm + OFF_P + (uint32_t)(((wq * 32 + (lane >> 2)) * LDP + ws * 32 + ((lane & 3) << 1)) << 1);
    // mask base (phase A role)
    const float* mBase = mask + ((size_t)(b * SQ + q0 + wq * 32 + (lane >> 2))) * SKV
                              + ws * 32 + ((lane & 3) << 1);

    float o[4][8][4];
#pragma unroll
    for (int mi = 0; mi < 4; mi++)
#pragma unroll
        for (int ni = 0; ni < 8; ni++) {
            o[mi][ni][0] = 0.f; o[mi][ni][1] = 0.f; o[mi][ni][2] = 0.f; o[mi][ni][3] = 0.f;
        }
    float lsum[4] = {0.f, 0.f, 0.f, 0.f};

    for (int it = 0; it < NIT; it++) {
        const uint32_t yoffC = (uint32_t)(it & 1) * SZ_Y;

        // (1) prefetch next Y tile into the other buffer
        if (it + 1 < NIT) {
            const __half* ysrc = yg + (size_t)(it + 1) * BK * D_DIM;
            const uint32_t ydst = sm + OFF_Y + (uint32_t)((it & 1) ^ 1) * SZ_Y;
#pragma unroll
            for (int i = 0; i < 16; i++) {
                int unit = tid + (i << 7);
                int r = unit >> 5, u = unit & 31;
                cpasync16(ydst + r * LDSB + u * 16, ysrc + (size_t)r * D_DIM + u * 8);
            }
            CP_COMMIT();
        }

        // (2) mask values for this tile (early issue, high MLP)
        float2 mv[2][2][4];
#pragma unroll
        for (int mi = 0; mi < 2; mi++)
#pragma unroll
            for (int hi = 0; hi < 2; hi++)
#pragma unroll
                for (int ni = 0; ni < 4; ni++)
                    mv[mi][hi][ni] = *reinterpret_cast<const float2*>(
                        mBase + (size_t)(mi * 16 + hi * 8) * SKV + (size_t)it * BK + ni * 8);

        // (3) phase A: S = Q @ K^T on Y[cur], warp tile 32x32, f32 accum
        float c[2][4][4];
#pragma unroll
        for (int mi = 0; mi < 2; mi++)
#pragma unroll
            for (int ni = 0; ni < 4; ni++) {
                c[mi][ni][0] = 0.f; c[mi][ni][1] = 0.f; c[mi][ni][2] = 0.f; c[mi][ni][3] = 0.f;
            }
#pragma unroll
        for (int ks = 0; ks < 16; ks++) {
            uint32_t a0[4], a1[4], b0[4], b1[4];
            ldsm4(a0, aX0 + (ks << 5));
            ldsm4(a1, aX1 + (ks << 5));
            ldsm4(b0, bS0 + yoffC + (ks << 5));
            ldsm4(b1, bS0 + yoffC + 16 * LDSB + (ks << 5));
            mma_f32(c[0][0], a0, b0[0], b0[1]);
            mma_f32(c[0][1], a0, b0[2], b0[3]);
            mma_f32(c[0][2], a0, b1[0], b1[1]);
            mma_f32(c[0][3], a0, b1[2], b1[3]);
            mma_f32(c[1][0], a1, b0[0], b0[1]);
            mma_f32(c[1][1], a1, b0[2], b0[3]);
            mma_f32(c[1][2], a1, b1[0], b1[1]);
            mma_f32(c[1][3], a1, b1[2], b1[3]);
        }

        // (4) softmax (no max shift: logits bounded) -> sP (fp16)
#pragma unroll
        for (int mi = 0; mi < 2; mi++)
#pragma unroll
            for (int hi = 0; hi < 2; hi++) {
                float acc = 0.f;
#pragma unroll
                for (int ni = 0; ni < 4; ni++) {
                    float p0 = ex2(c[mi][ni][hi * 2 + 0] * mv[mi][hi][ni].x * KC);
                    float p1 = ex2(c[mi][ni][hi * 2 + 1] * mv[mi][hi][ni].y * KC);
                    acc += p0 + p1;
                    __half2 hh = __floats2half2_rn(p0, p1);
                    *reinterpret_cast<__half2*>(
                        smem_raw + (pSt - sm) + (mi * 16 + hi * 8) * LDPB + ni * 16) = hh;
                }
                lsum[mi * 2 + hi] += acc;
            }
        __syncthreads();   // P visible (Y[cur] still in use; prefetch hits other buf)

        // (5) phase B: O += P @ Y[cur], warp tile 64x64
#pragma unroll
        for (int ks = 0; ks < 4; ks++) {
            uint32_t a[4][4];
#pragma unroll
            for (int mi = 0; mi < 4; mi++)
                ldsm4(a[mi], aP + mi * 16 * LDPB + (ks << 5));
#pragma unroll
            for (int t2 = 0; t2 < 4; t2++) {
                uint32_t bb[4];
                ldsm4t(bb, bV + yoffC + ks * 16 * LDSB + (t2 << 5));
#pragma unroll
                for (int mi = 0; mi < 4; mi++) {
                    mma_f32(o[mi][2 * t2],     a[mi], bb[0], bb[1]);
                    mma_f32(o[mi][2 * t2 + 1], a[mi], bb[2], bb[3]);
                }
            }
        }

        // (6) Y[next] landed; P free; Y[cur] free after this point
        if (it + 1 < NIT) CP_WAIT0();
        __syncthreads();
    }

    // ---------- epilogue: reduce l, write out = O/l + x ----------
#pragma unroll
    for (int s = 0; s < 4; s++) {
        float v = lsum[s];
        v += __shfl_xor_sync(0xffffffffu, v, 1);
        v += __shfl_xor_sync(0xffffffffu, v, 2);
        if ((lane & 3) == 0)
            sL[ws * BQ + wq * 32 + (s >> 1) * 16 + (s & 1) * 8 + (lane >> 2)] = v;
    }
    __syncthreads();

#pragma unroll
    for (int mi = 0; mi < 4; mi++)
#pragma unroll
        for (int hi = 0; hi < 2; hi++) {
            const int r = mi * 16 + hi * 8 + (lane >> 2);
            const float inv = 1.f / (sL[r] + sL[BQ + r]);
            const size_t gr = (size_t)b * SQ + q0 + r;
            const float* xr = x + gr * D_DIM + wd * 64 + ((lane & 3) << 1);
            float* og = out + gr * D_DIM + wd * 64 + ((lane & 3) << 1);
#pragma unroll
            for (int ni = 0; ni < 8; ni++) {
                float2 xv = *reinterpret_cast<const float2*>(xr + ni * 8);
                float2 w;
                w.x = o[mi][ni][hi * 2 + 0] * inv + xv.x;
                w.y = o[mi][ni][hi * 2 + 1] * inv + xv.y;
                *reinterpret_cast<float2*>(og + ni * 8) = w;
            }
        }
}

extern "C" void kernel_launch(void* const* d_in, const int* in_sizes, int n_in,
                              void* d_out, int out_size) {
    const float* x    = (const float*)d_in[0];
    const float* y    = (const float*)d_in[1];
    const float* mask = (const float*)d_in[2];
    float* out        = (float*)d_out;

    // y fp32 -> fp16 (x is converted inside fa_kernel's prologue)
    convert_y<<<(B_DIM * SKV * D_DIM) / (256 * 16), 256>>>(y);

    cudaFuncSetAttribute(fa_kernel, cudaFuncAttributeMaxDynamicSharedMemorySize, SMEM_BYTES);
    dim3 grid(SQ / BQ, B_DIM);
    fa_kernel<<<grid, NTHR, SMEM_BYTES>>>(x, mask, out);
}

// round 16
// speedup vs baseline: 1.9569x; 1.0368x over previous
#include <cuda_runtime.h>
#include <cuda_fp16.h>
#include <cstdint>
#include <math.h>

#define B_DIM 16
#define SQ    2048
#define SKV   2048
#define D_DIM 256
#define BQ    64
#define BK    64
#define NIT   (SKV / BK)
#define KC    (0.022097086912079608f * 1.4426950408889634f)  // (1/sqrt(2048)) * log2(e)

#define NTHR  128

#define LDS   264          // sQ/sY row stride (fp16 elems), 528B
#define LDSB  528
#define LDP   72           // sP row stride (fp16 elems), 144B
#define LDPB  144

// smem layout (bytes) — sized so TWO CTAs fit per SM (2x111104 = 222208 <= 228KB)
#define OFF_Q 0
#define SZ_Q  (BQ * LDSB)                // 33792
#define OFF_Y (OFF_Q + SZ_Q)
#define SZ_Y  (BK * LDSB)                // 33792 per buffer (x2)
#define OFF_P (OFF_Y + 2 * SZ_Y)         // 101376
#define SZ_P  (BQ * LDPB)                // 9216 (single buffer)
#define OFF_L (OFF_P + SZ_P)             // 110592
#define SMEM_BYTES (OFF_L + 2 * BQ * 4)  // 111104

__device__ __half g_yh[(size_t)B_DIM * SKV * D_DIM];

__device__ __forceinline__ uint32_t sptr(const void* p) {
    return (uint32_t)__cvta_generic_to_shared(p);
}

__device__ __forceinline__ void ldsm4(uint32_t* r, uint32_t a) {
    asm("ldmatrix.sync.aligned.m8n8.x4.shared.b16 {%0,%1,%2,%3}, [%4];"
        : "=r"(r[0]), "=r"(r[1]), "=r"(r[2]), "=r"(r[3]) : "r"(a) : "memory");
}
__device__ __forceinline__ void ldsm4t(uint32_t* r, uint32_t a) {
    asm("ldmatrix.sync.aligned.m8n8.x4.trans.shared.b16 {%0,%1,%2,%3}, [%4];"
        : "=r"(r[0]), "=r"(r[1]), "=r"(r[2]), "=r"(r[3]) : "r"(a) : "memory");
}
__device__ __forceinline__ void mma_f32(float* c, const uint32_t* a, uint32_t b0, uint32_t b1) {
    asm("mma.sync.aligned.m16n8k16.row.col.f32.f16.f16.f32 "
        "{%0,%1,%2,%3}, {%4,%5,%6,%7}, {%8,%9}, {%0,%1,%2,%3};"
        : "+f"(c[0]), "+f"(c[1]), "+f"(c[2]), "+f"(c[3])
        : "r"(a[0]), "r"(a[1]), "r"(a[2]), "r"(a[3]), "r"(b0), "r"(b1));
}
// packed fp16 exp2 (ex2.approx.f16x2, sm_75+)
__device__ __forceinline__ __half2 h2ex2(__half2 v) {
    uint32_t r, a = *reinterpret_cast<uint32_t*>(&v);
    asm("ex2.approx.f16x2 %0, %1;" : "=r"(r) : "r"(a));
    return *reinterpret_cast<__half2*>(&r);
}
__device__ __forceinline__ void cpasync16(uint32_t dst, const void* src) {
    asm volatile("cp.async.cg.shared.global [%0], [%1], 16;" :: "r"(dst), "l"(src) : "memory");
}
#define CP_COMMIT() asm volatile("cp.async.commit_group;" ::: "memory")
#define CP_WAIT0()  asm volatile("cp.async.wait_group 0;" ::: "memory")

// -------- pre-convert fp32 -> fp16 for y only (x handled in fa prologue) ----
__global__ void __launch_bounds__(256) convert_y(const float* __restrict__ y) {
    size_t base = ((size_t)blockIdx.x * 256 + threadIdx.x) * 4;
    const size_t stride = (size_t)gridDim.x * 256 * 4;
#pragma unroll
    for (int j = 0; j < 4; j++) {
        size_t i = base + (size_t)j * stride;
        float4 f = *reinterpret_cast<const float4*>(y + i);
        __half2 h0 = __floats2half2_rn(f.x, f.y);
        __half2 h1 = __floats2half2_rn(f.z, f.w);
        uint2 u;
        u.x = *reinterpret_cast<uint32_t*>(&h0);
        u.y = *reinterpret_cast<uint32_t*>(&h1);
        *reinterpret_cast<uint2*>(g_yh + i) = u;
    }
}

extern __shared__ char smem_raw[];

__global__ void __launch_bounds__(NTHR, 2)
fa_kernel(const float* __restrict__ x, const float* __restrict__ mask,
          float* __restrict__ out) {
    const int tid  = threadIdx.x;
    const int lane = tid & 31;
    const int warp = tid >> 5;          // 0..3
    // phase A roles: 2 q-groups x 2 kv-halves, warp tile 32x32
    const int wq = warp >> 1;
    const int ws = warp & 1;
    // phase B roles: all 4 warps share q 0..63; each owns 64 of d=256
    const int wd = warp;

    const int b  = blockIdx.y;
    const int q0 = blockIdx.x * BQ;

    const uint32_t sm = sptr(smem_raw);
    float* sL = reinterpret_cast<float*>(smem_raw + OFF_L);

    // ---- prologue ----
    // Y tile 0 via cp.async (fp16 source); Q from fp32 x, converted inline.
    const float* xg32 = x + ((size_t)b * SQ + q0) * D_DIM;
    const __half* yg  = g_yh + (size_t)b * SKV * D_DIM;
#pragma unroll
    for (int i = 0; i < 16; i++) {
        int unit = tid + (i << 7);
        int r = unit >> 5, u = unit & 31;
        cpasync16(sm + OFF_Y + r * LDSB + u * 16, yg + (size_t)r * D_DIM + u * 8);
    }
    CP_COMMIT();
#pragma unroll
    for (int i = 0; i < 16; i++) {
        int unit = tid + (i << 7);      // 2048 units of 16B-fp16 (32 per row)
        int r = unit >> 5, u = unit & 31;
        const float* src = xg32 + (size_t)r * D_DIM + u * 8;
        float4 f0 = reinterpret_cast<const float4*>(src)[0];
        float4 f1 = reinterpret_cast<const float4*>(src)[1];
        __half2 h0 = __floats2half2_rn(f0.x, f0.y);
        __half2 h1 = __floats2half2_rn(f0.z, f0.w);
        __half2 h2 = __floats2half2_rn(f1.x, f1.y);
        __half2 h3 = __floats2half2_rn(f1.z, f1.w);
        uint4 v;
        v.x = *reinterpret_cast<uint32_t*>(&h0);
        v.y = *reinterpret_cast<uint32_t*>(&h1);
        v.z = *reinterpret_cast<uint32_t*>(&h2);
        v.w = *reinterpret_cast<uint32_t*>(&h3);
        *reinterpret_cast<uint4*>(smem_raw + OFF_Q + r * LDSB + u * 16) = v;
    }
    CP_WAIT0();
    __syncthreads();

    // ---- precomputed addresses ----
    const int jb = lane >> 3;
    // phase A: A frags from sQ (rows wq*32.., two 16-row halves)
    const uint32_t aX0 = sm + OFF_Q + (uint32_t)(((wq * 32 + (lane & 15)) * LDS + ((lane >> 4) << 3)) << 1);
    const uint32_t aX1 = aX0 + 16 * LDSB;
    // phase A: B frags from sY (kv rows ws*32..), k = d, non-trans
    const int bRow = (lane & 7) + ((jb >> 1) << 3);
    const int bCol = (jb & 1) << 3;
    const uint32_t bS0 = sm + OFF_Y + (uint32_t)(((ws * 32 + bRow) * LDS + bCol) << 1);
    // phase B: A frags from sP (rows 0..63)
    const uint32_t aP = sm + OFF_P + (uint32_t)((((lane & 15)) * LDP + ((lane >> 4) << 3)) << 1);
    // phase B: B frags from sY, k = kv, n = d -> trans
    const int vRow = (lane & 7) + ((jb & 1) << 3);
    const int vCol = ((jb >> 1) << 3) + wd * 64;
    const uint32_t bV = sm + OFF_Y + (uint32_t)(((vRow * LDS) + vCol) << 1);
    // P store base (phase A role)
    const uint32_t pSt = sm + OFF_P + (uint32_t)(((wq * 32 + (lane >> 2)) * LDP + ws * 32 + ((lane & 3) << 1)) << 1);
    // mask base (phase A role)
    const float* mBase = mask + ((size_t)(b * SQ + q0 + wq * 32 + (lane >> 2))) * SKV
                              + ws * 32 + ((lane & 3) << 1);

    float o[4][8][4];
#pragma unroll
    for (int mi = 0; mi < 4; mi++)
#pragma unroll
        for (int ni = 0; ni < 8; ni++) {
            o[mi][ni][0] = 0.f; o[mi][ni][1] = 0.f; o[mi][ni][2] = 0.f; o[mi][ni][3] = 0.f;
        }
    float lsum[4] = {0.f, 0.f, 0.f, 0.f};

    for (int it = 0; it < NIT; it++) {
        const uint32_t yoffC = (uint32_t)(it & 1) * SZ_Y;

        // (1) prefetch next Y tile into the other buffer
        if (it + 1 < NIT) {
            const __half* ysrc = yg + (size_t)(it + 1) * BK * D_DIM;
            const uint32_t ydst = sm + OFF_Y + (uint32_t)((it & 1) ^ 1) * SZ_Y;
#pragma unroll
            for (int i = 0; i < 16; i++) {
                int unit = tid + (i << 7);
                int r = unit >> 5, u = unit & 31;
                cpasync16(ydst + r * LDSB + u * 16, ysrc + (size_t)r * D_DIM + u * 8);
            }
            CP_COMMIT();
        }

        // (2) mask values for this tile (early issue, high MLP)
        float2 mv[2][2][4];
#pragma unroll
        for (int mi = 0; mi < 2; mi++)
#pragma unroll
            for (int hi = 0; hi < 2; hi++)
#pragma unroll
                for (int ni = 0; ni < 4; ni++)
                    mv[mi][hi][ni] = *reinterpret_cast<const float2*>(
                        mBase + (size_t)(mi * 16 + hi * 8) * SKV + (size_t)it * BK + ni * 8);

        // (3) phase A: S = Q @ K^T on Y[cur], warp tile 32x32, f32 accum
        float c[2][4][4];
#pragma unroll
        for (int mi = 0; mi < 2; mi++)
#pragma unroll
            for (int ni = 0; ni < 4; ni++) {
                c[mi][ni][0] = 0.f; c[mi][ni][1] = 0.f; c[mi][ni][2] = 0.f; c[mi][ni][3] = 0.f;
            }
#pragma unroll
        for (int ks = 0; ks < 16; ks++) {
            uint32_t a0[4], a1[4], b0[4], b1[4];
            ldsm4(a0, aX0 + (ks << 5));
            ldsm4(a1, aX1 + (ks << 5));
            ldsm4(b0, bS0 + yoffC + (ks << 5));
            ldsm4(b1, bS0 + yoffC + 16 * LDSB + (ks << 5));
            mma_f32(c[0][0], a0, b0[0], b0[1]);
            mma_f32(c[0][1], a0, b0[2], b0[3]);
            mma_f32(c[0][2], a0, b1[0], b1[1]);
            mma_f32(c[0][3], a0, b1[2], b1[3]);
            mma_f32(c[1][0], a1, b0[0], b0[1]);
            mma_f32(c[1][1], a1, b0[2], b0[3]);
            mma_f32(c[1][2], a1, b1[0], b1[1]);
            mma_f32(c[1][3], a1, b1[2], b1[3]);
        }

        // (4) softmax, packed-fp16 path:
        //     logit pair = cvt_f16x2(c) * cvt_f16x2(mask*KC); p = ex2.f16x2.
        //     |logit| <= ~13 -> fp16-safe; p <= ~735 -> no overflow.
#pragma unroll
        for (int mi = 0; mi < 2; mi++)
#pragma unroll
            for (int hi = 0; hi < 2; hi++) {
                __half2 hacc = __floats2half2_rn(0.f, 0.f);
#pragma unroll
                for (int ni = 0; ni < 4; ni++) {
                    __half2 mh = __floats2half2_rn(mv[mi][hi][ni].x * KC,
                                                   mv[mi][hi][ni].y * KC);
                    __half2 ch = __floats2half2_rn(c[mi][ni][hi * 2 + 0],
                                                   c[mi][ni][hi * 2 + 1]);
                    __half2 p  = h2ex2(__hmul2(ch, mh));
                    *reinterpret_cast<__half2*>(
                        smem_raw + (pSt - sm) + (mi * 16 + hi * 8) * LDPB + ni * 16) = p;
                    hacc = __hadd2(hacc, p);
                }
                float2 fa2 = __half22float2(hacc);
                lsum[mi * 2 + hi] += fa2.x + fa2.y;
            }
        __syncthreads();   // P visible (Y[cur] still in use; prefetch hits other buf)

        // (5) phase B: O += P @ Y[cur], warp tile 64x64
#pragma unroll
        for (int ks = 0; ks < 4; ks++) {
            uint32_t a[4][4];
#pragma unroll
            for (int mi = 0; mi < 4; mi++)
                ldsm4(a[mi], aP + mi * 16 * LDPB + (ks << 5));
#pragma unroll
            for (int t2 = 0; t2 < 4; t2++) {
                uint32_t bb[4];
                ldsm4t(bb, bV + yoffC + ks * 16 * LDSB + (t2 << 5));
#pragma unroll
                for (int mi = 0; mi < 4; mi++) {
                    mma_f32(o[mi][2 * t2],     a[mi], bb[0], bb[1]);
                    mma_f32(o[mi][2 * t2 + 1], a[mi], bb[2], bb[3]);
                }
            }
        }

        // (6) Y[next] landed; P free; Y[cur] free after this point
        if (it + 1 < NIT) CP_WAIT0();
        __syncthreads();
    }

    // ---------- epilogue: reduce l, write out = O/l + x ----------
#pragma unroll
    for (int s = 0; s < 4; s++) {
        float v = lsum[s];
        v += __shfl_xor_sync(0xffffffffu, v, 1);
        v += __shfl_xor_sync(0xffffffffu, v, 2);
        if ((lane & 3) == 0)
            sL[ws * BQ + wq * 32 + (s >> 1) * 16 + (s & 1) * 8 + (lane >> 2)] = v;
    }
    __syncthreads();

#pragma unroll
    for (int mi = 0; mi < 4; mi++)
#pragma unroll
        for (int hi = 0; hi < 2; hi++) {
            const int r = mi * 16 + hi * 8 + (lane >> 2);
            const float inv = 1.f / (sL[r] + sL[BQ + r]);
            const size_t gr = (size_t)b * SQ + q0 + r;
            const float* xr = x + gr * D_DIM + wd * 64 + ((lane & 3) << 1);
            float* og = out + gr * D_DIM + wd * 64 + ((lane & 3) << 1);
#pragma unroll
            for (int ni = 0; ni < 8; ni++) {
                float2 xv = *reinterpret_cast<const float2*>(xr + ni * 8);
                float2 w;
                w.x = o[mi][ni][hi * 2 + 0] * inv + xv.x;
                w.y = o[mi][ni][hi * 2 + 1] * inv + xv.y;
                *reinterpret_cast<float2*>(og + ni * 8) = w;
            }
        }
}

extern "C" void kernel_launch(void* const* d_in, const int* in_sizes, int n_in,
                              void* d_out, int out_size) {
    const float* x    = (const float*)d_in[0];
    const float* y    = (const float*)d_in[1];
    const float* mask = (const float*)d_in[2];
    float* out        = (float*)d_out;

    // y fp32 -> fp16 (x is converted inside fa_kernel's prologue)
    convert_y<<<(B_DIM * SKV * D_DIM) / (256 * 16), 256>>>(y);

    cudaFuncSetAttribute(fa_kernel, cudaFuncAttributeMaxDynamicSharedMemorySize, SMEM_BYTES);
    dim3 grid(SQ / BQ, B_DIM);
    fa_kernel<<<grid, NTHR, SMEM_BYTES>>>(x, mask, out);
}